// round 14
// baseline (speedup 1.0000x reference)
#include <cuda_runtime.h>
#include <cuda_fp16.h>
#include <cstdint>

#define DIN    128
#define DOUT   128
#define TILE   64
#define THREADS 256
#define NST    2

// ---- smem layout (per CTA ~67KB -> 2 CTAs/SM) ----
#define OFF_WH     0                          // 8s x 8pairs x 32 x 16B = 32KB
#define AH_ST(s)   (32768 + (s)*16384)        // 16KB/stage: 64 rows x 256B fp16 (swizzled)
#define OFF_BIAS   65536                      // 128 f32
#define OFF_B2     66048
#define OFF_XN2    66064                      // [64] f32 (consumer-written)
#define OFF_RS2    66320                      // [64][4] f32
#define OFF_RSB    67344                      // [64][4] f32
#define OFF_CA     68368
#define OFF_CB     68624
#define SMEM_TOTAL 68880

// named barriers: 1,2 = full(stage), 3,4 = empty(stage), 5 = consumer-internal
#define BAR_FULL(s)  (1 + (s))
#define BAR_EMPTY(s) (3 + (s))
#define BAR_CONS     5

__device__ __forceinline__ void bar_sync256(int id) {
    asm volatile("bar.sync %0, %1;" :: "r"(id), "r"(256) : "memory");
}
__device__ __forceinline__ void bar_arrive256(int id) {
    asm volatile("bar.arrive %0, %1;" :: "r"(id), "r"(256) : "memory");
}
__device__ __forceinline__ void bar_sync128(int id) {
    asm volatile("bar.sync %0, %1;" :: "r"(id), "r"(128) : "memory");
}
__device__ __forceinline__ unsigned smem_u32(const void* p) {
    return (unsigned)__cvta_generic_to_shared(p);
}
__device__ __forceinline__ uint32_t packh(float hi, float lo) {
    uint32_t r; asm("cvt.rn.f16x2.f32 %0, %1, %2;" : "=r"(r) : "f"(hi), "f"(lo)); return r;
}
__device__ __forceinline__ void mma_f16(float4& d, const uint4& a, uint32_t b0, uint32_t b1) {
    asm volatile("mma.sync.aligned.m16n8k16.row.col.f32.f16.f16.f32 "
        "{%0,%1,%2,%3}, {%4,%5,%6,%7}, {%8,%9}, {%0,%1,%2,%3};"
        : "+f"(d.x), "+f"(d.y), "+f"(d.z), "+f"(d.w)
        : "r"(a.x), "r"(a.y), "r"(a.z), "r"(a.w), "r"(b0), "r"(b1));
}
__device__ __forceinline__ void ldm_x4(uint4& a, uint32_t addr) {
    asm volatile("ldmatrix.sync.aligned.m8n8.x4.shared.b16 {%0,%1,%2,%3}, [%4];"
        : "=r"(a.x), "=r"(a.y), "=r"(a.z), "=r"(a.w) : "r"(addr));
}
__device__ __forceinline__ float sq2(uint32_t h2, float acc) {
    float2 f = __half22float2(*(__half2*)&h2);
    return fmaf(f.x, f.x, fmaf(f.y, f.y, acc));
}

extern "C" __global__ void __launch_bounds__(THREADS, 2)
mobius_perm_kernel(const float* __restrict__ X,
                   const float* __restrict__ W,
                   const float* __restrict__ bias,
                   float* __restrict__ out,
                   int nrows)
{
    extern __shared__ __align__(16) char smem[];
    float* sbias = (float*)(smem + OFF_BIAS);
    float* sB2   = (float*)(smem + OFF_B2);
    float* xn2s  = (float*)(smem + OFF_XN2);
    float* rs2   = (float*)(smem + OFF_RS2);
    float* rsb   = (float*)(smem + OFF_RSB);
    float* cA    = (float*)(smem + OFF_CA);
    float* cB    = (float*)(smem + OFF_CB);

    const int tid  = threadIdx.x;
    const int lane = tid & 31;
    const int wid  = tid >> 5;
    const int g    = lane >> 2;
    const int cg   = lane & 3;

    if (tid < 128) sbias[tid] = bias[tid];

    // ---- W conversion (once): warp wid = k-step s; COLUMN-PERMUTED ----
    // Frag position (pair p, n_idx=g, half) holds logical output column
    //   n_log = (p>>1)*32 + (g>>1)*8 + (p&1)*4 + half*2 + (g&1)
    // so each consumer lane's accumulator columns are CONTIGUOUS.
    {
        #pragma unroll
        for (int p = 0; p < 8; p++) {
            #pragma unroll
            for (int half = 0; half < 2; half++) {
                int n_log = (p >> 1) * 32 + (g >> 1) * 8 + (p & 1) * 4
                          + half * 2 + (g & 1);
                const float* wp = W + n_log * DIN + wid * 16 + 2 * cg;
                float2 u0 = *(const float2*)(wp);
                float2 u1 = *(const float2*)(wp + 8);
                uint2 vh;
                vh.x = packh(u0.y, u0.x);
                vh.y = packh(u1.y, u1.x);
                *(uint2*)(smem + OFF_WH + ((wid * 8 + p) * 32 + lane) * 16 + half * 8) = vh;
            }
        }
    }
    __syncthreads();
    if (tid < 32) {
        float s = 0.f;
        #pragma unroll
        for (int i = 0; i < 4; i++) { float v = sbias[tid + 32 * i]; s = fmaf(v, v, s); }
        #pragma unroll
        for (int o = 16; o; o >>= 1) s += __shfl_xor_sync(0xffffffffu, s, o);
        if (tid == 0) *sB2 = s;
    }
    __syncthreads();   // last CTA-wide barrier

    const int ntiles = nrows / TILE;
    const int gstep  = gridDim.x;

    if (wid < 4) {
        // ===== PRODUCER: pure stream, coalesced rows -> swizzled fp16 =====
        const int p = wid;                // rows p*16 .. p*16+15
        const int ch0 = lane >> 1;        // 16B chunk within row
        const int sub = (lane & 1) * 8;   // 8B half within chunk
        int i = 0;
        for (int t = blockIdx.x; t < ntiles; t += gstep, i++) {
            const int st = i & (NST - 1);
            if (i >= NST) bar_sync256(BAR_EMPTY(st));

            const long long rowbase = (long long)t * TILE;
            const float* xp = X + (rowbase + p * 16) * DIN + lane * 4;
            char* abuf = smem + AH_ST(st);
            #pragma unroll
            for (int r = 0; r < 16; r++) {
                float4 v = *(const float4*)(xp + r * DIN);
                uint2 u;
                u.x = packh(v.y, v.x);
                u.y = packh(v.w, v.z);
                int rw = p * 16 + r;
                int sw = ch0 ^ (rw & 7);
                *(uint2*)(abuf + rw * 256 + sw * 16 + sub) = u;
            }
            __threadfence_block();
            bar_arrive256(BAR_FULL(st));
        }
    } else {
        // ===== CONSUMER: ldmatrix A + MMA (m64 x n32) + xn2 + epilogue =====
        const int c    = wid - 4;      // n-quarter: cols c*32 .. c*32+31
        const int ctid = tid - 128;
        const float b2c = *sB2;

        const int rloc = ((lane >> 3) & 1) * 8 + (lane & 7);
        const int hk   = lane >> 4;

        // permuted bias frags: lane's cols are c*32 + 8cg + 2j + {0,1}
        float2 bj[4];
        #pragma unroll
        for (int j = 0; j < 4; j++)
            bj[j] = *(const float2*)(sbias + c * 32 + cg * 8 + 2 * j);

        int i = 0;
        for (int t = blockIdx.x; t < ntiles; t += gstep, i++) {
            const int st = i & (NST - 1);
            const long long rowbase = (long long)t * TILE;

            bar_sync256(BAR_FULL(st));

            const uint32_t abase = smem_u32(smem + AH_ST(st));

            // ---- mainloop: 1-pass fp16, warp tile m64 x n32; xs2 for ii==c
            float4 acc[4][4];
            #pragma unroll
            for (int ii = 0; ii < 4; ii++)
                #pragma unroll
                for (int j = 0; j < 4; j++) acc[ii][j] = make_float4(0.f, 0.f, 0.f, 0.f);
            float xs2r0 = 0.f, xs2r1 = 0.f;

            #pragma unroll
            for (int s = 0; s < 8; s++) {
                uint4 ah[4], wh[2];
                #pragma unroll
                for (int ii = 0; ii < 4; ii++) {
                    int row = ii * 16 + rloc;
                    int ch  = (s * 2 + hk) ^ (row & 7);
                    ldm_x4(ah[ii], abase + row * 256 + ch * 16);
                }
                #pragma unroll
                for (int u = 0; u < 2; u++)
                    wh[u] = *(const uint4*)(smem + OFF_WH
                              + ((s * 8 + c * 2 + u) * 32 + lane) * 16);
                #pragma unroll
                for (int ii = 0; ii < 4; ii++)
                    #pragma unroll
                    for (int u = 0; u < 2; u++) {
                        mma_f16(acc[ii][2*u],   ah[ii], wh[u].x, wh[u].y);
                        mma_f16(acc[ii][2*u+1], ah[ii], wh[u].z, wh[u].w);
                    }
                #pragma unroll
                for (int ii = 0; ii < 4; ii++) {
                    if (ii == c) {
                        xs2r0 = sq2(ah[ii].x, xs2r0);
                        xs2r1 = sq2(ah[ii].y, xs2r1);
                        xs2r0 = sq2(ah[ii].z, xs2r0);
                        xs2r1 = sq2(ah[ii].w, xs2r1);
                    }
                }
            }

            // ---- reductions per row ----
            xs2r0 += __shfl_xor_sync(0xffffffffu, xs2r0, 1);
            xs2r0 += __shfl_xor_sync(0xffffffffu, xs2r0, 2);
            xs2r1 += __shfl_xor_sync(0xffffffffu, xs2r1, 1);
            xs2r1 += __shfl_xor_sync(0xffffffffu, xs2r1, 2);
            if (cg == 0) {
                xn2s[c * 16 + g]     = xs2r0;
                xn2s[c * 16 + g + 8] = xs2r1;
            }

            #pragma unroll
            for (int ii = 0; ii < 4; ii++) {
                float s2r0 = 0.f, s2r1 = 0.f, sbr0 = 0.f, sbr1 = 0.f;
                #pragma unroll
                for (int j = 0; j < 4; j++) {
                    float4 d = acc[ii][j];
                    s2r0 = fmaf(d.x, d.x, s2r0); s2r0 = fmaf(d.y, d.y, s2r0);
                    s2r1 = fmaf(d.z, d.z, s2r1); s2r1 = fmaf(d.w, d.w, s2r1);
                    sbr0 = fmaf(d.x, bj[j].x, sbr0); sbr0 = fmaf(d.y, bj[j].y, sbr0);
                    sbr1 = fmaf(d.z, bj[j].x, sbr1); sbr1 = fmaf(d.w, bj[j].y, sbr1);
                }
                s2r0 += __shfl_xor_sync(0xffffffffu, s2r0, 1);
                s2r0 += __shfl_xor_sync(0xffffffffu, s2r0, 2);
                s2r1 += __shfl_xor_sync(0xffffffffu, s2r1, 1);
                s2r1 += __shfl_xor_sync(0xffffffffu, s2r1, 2);
                sbr0 += __shfl_xor_sync(0xffffffffu, sbr0, 1);
                sbr0 += __shfl_xor_sync(0xffffffffu, sbr0, 2);
                sbr1 += __shfl_xor_sync(0xffffffffu, sbr1, 1);
                sbr1 += __shfl_xor_sync(0xffffffffu, sbr1, 2);
                if (cg == 0) {
                    int r0 = ii * 16 + g;
                    rs2[r0 * 4 + c]       = s2r0;
                    rs2[(r0 + 8) * 4 + c] = s2r1;
                    rsb[r0 * 4 + c]       = sbr0;
                    rsb[(r0 + 8) * 4 + c] = sbr1;
                }
            }
            bar_sync128(BAR_CONS);

            // ---- per-row coefficients ----
            if (ctid < TILE) {
                int r = ctid;
                float4 a4 = *(const float4*)(rs2 + r * 4);
                float4 b4 = *(const float4*)(rsb + r * 4);
                float mxn2 = (a4.x + a4.y) + (a4.z + a4.w);
                float dotb = (b4.x + b4.y) + (b4.z + b4.w);
                float xn  = fmaxf(sqrtf(xn2s[r]), 1e-15f);
                float mxn = fmaxf(sqrtf(mxn2),    1e-15f);
                float u   = fminf(xn, 1.0f - 1e-7f);
                float at  = 0.5f * (log1pf(u) - log1pf(-u));
                float sc  = tanhf(mxn / xn * at) / mxn;
                if (mxn <= 1e-10f) sc = 0.0f;
                float xy    = sc * dotb;
                float y2    = sc * sc * mxn2;
                float alpha = 1.0f + 2.0f * xy + b2c;
                float beta  = 1.0f - y2;
                float den   = fmaxf(1.0f + 2.0f * xy + y2 * b2c, 1e-15f);
                float A  = sc * alpha / den;
                float Bc = beta / den;
                float o2 = A * A * mxn2 + 2.0f * A * Bc * dotb + Bc * Bc * b2c;
                float on = fmaxf(sqrtf(o2), 1e-15f);
                float mxv = 1.0f - 1e-5f;
                float fpr = (on > mxv) ? (mxv / on) : 1.0f;
                cA[r] = A * fpr;
                cB[r] = Bc * fpr;
            }
            bar_sync128(BAR_CONS);

            // stage fully consumed
            if (t + NST * gstep < ntiles)
                bar_arrive256(BAR_EMPTY(st));

            // ---- stores: contiguous 8 cols per lane -> STG.128 x2 per row
            #pragma unroll
            for (int ii = 0; ii < 4; ii++) {
                int r0 = ii * 16 + g;
                float A0 = cA[r0],     B0 = cB[r0];
                float A1 = cA[r0 + 8], B1 = cB[r0 + 8];
                float* op0 = out + (rowbase + r0) * DOUT + c * 32 + 8 * cg;
                float* op1 = op0 + 8 * DOUT;
                float4 v0, v1, w0, w1;
                v0.x = fmaf(A0, acc[ii][0].x, B0 * bj[0].x);
                v0.y = fmaf(A0, acc[ii][0].y, B0 * bj[0].y);
                v0.z = fmaf(A0, acc[ii][1].x, B0 * bj[1].x);
                v0.w = fmaf(A0, acc[ii][1].y, B0 * bj[1].y);
                v1.x = fmaf(A0, acc[ii][2].x, B0 * bj[2].x);
                v1.y = fmaf(A0, acc[ii][2].y, B0 * bj[2].y);
                v1.z = fmaf(A0, acc[ii][3].x, B0 * bj[3].x);
                v1.w = fmaf(A0, acc[ii][3].y, B0 * bj[3].y);
                w0.x = fmaf(A1, acc[ii][0].z, B1 * bj[0].x);
                w0.y = fmaf(A1, acc[ii][0].w, B1 * bj[0].y);
                w0.z = fmaf(A1, acc[ii][1].z, B1 * bj[1].x);
                w0.w = fmaf(A1, acc[ii][1].w, B1 * bj[1].y);
                w1.x = fmaf(A1, acc[ii][2].z, B1 * bj[2].x);
                w1.y = fmaf(A1, acc[ii][2].w, B1 * bj[2].y);
                w1.z = fmaf(A1, acc[ii][3].z, B1 * bj[3].x);
                w1.w = fmaf(A1, acc[ii][3].w, B1 * bj[3].y);
                *(float4*)(op0)     = v0;
                *(float4*)(op0 + 4) = v1;
                *(float4*)(op1)     = w0;
                *(float4*)(op1 + 4) = w1;
            }
            // cA/cB/xn2 reuse safe: next writes happen after the next
            // BAR_CONS pair, which this warp reaches only after stores issue.
        }
    }
}

extern "C" void kernel_launch(void* const* d_in, const int* in_sizes, int n_in,
                              void* d_out, int out_size) {
    const float* X    = (const float*)d_in[0];
    const float* W    = (const float*)d_in[1];
    const float* bias = (const float*)d_in[2];
    float* out = (float*)d_out;

    int nrows = in_sizes[0] / DIN;

    cudaFuncSetAttribute(mobius_perm_kernel,
                         cudaFuncAttributeMaxDynamicSharedMemorySize, SMEM_TOTAL);

    int nsm = 148;
    cudaDeviceGetAttribute(&nsm, cudaDevAttrMultiProcessorCount, 0);
    int ntiles = nrows / TILE;
    int grid = 2 * nsm;
    if (grid > ntiles) grid = ntiles;

    mobius_perm_kernel<<<grid, THREADS, SMEM_TOTAL>>>(X, W, bias, out, nrows);
}

// round 15
// speedup vs baseline: 1.0906x; 1.0906x over previous
#include <cuda_runtime.h>
#include <cuda_fp16.h>
#include <cstdint>

#define DIN    128
#define DOUT   128
#define TILE   64
#define THREADS 384
#define NST    2

// ---- smem layout (per CTA ~67KB -> 2 CTAs/SM) ----
#define OFF_WH     0                          // 8s x 8pairs x 32 x 16B = 32KB
#define AH_ST(s)   (32768 + (s)*16384)        // 16KB/stage: 64 rows x 256B fp16 (swizzled)
#define OFF_BIAS   65536                      // 128 f32
#define OFF_B2     66048
#define OFF_XN2    66064                      // [64] f32 (consumer-written)
#define OFF_RS2    66320                      // [64][4] f32
#define OFF_RSB    67344                      // [64][4] f32
#define OFF_CA     68368
#define OFF_CB     68624
#define SMEM_TOTAL 68880

// named barriers: 1,2 = full(stage), 3,4 = empty(stage), 5 = consumer-internal
#define BAR_FULL(s)  (1 + (s))
#define BAR_EMPTY(s) (3 + (s))
#define BAR_CONS     5

__device__ __forceinline__ void bar_sync(int id, int n) {
    asm volatile("bar.sync %0, %1;" :: "r"(id), "r"(n) : "memory");
}
__device__ __forceinline__ void bar_arrive(int id, int n) {
    asm volatile("bar.arrive %0, %1;" :: "r"(id), "r"(n) : "memory");
}
__device__ __forceinline__ unsigned smem_u32(const void* p) {
    return (unsigned)__cvta_generic_to_shared(p);
}
__device__ __forceinline__ uint32_t packh(float hi, float lo) {
    uint32_t r; asm("cvt.rn.f16x2.f32 %0, %1, %2;" : "=r"(r) : "f"(hi), "f"(lo)); return r;
}
__device__ __forceinline__ void mma_f16(float4& d, const uint4& a, uint32_t b0, uint32_t b1) {
    asm volatile("mma.sync.aligned.m16n8k16.row.col.f32.f16.f16.f32 "
        "{%0,%1,%2,%3}, {%4,%5,%6,%7}, {%8,%9}, {%0,%1,%2,%3};"
        : "+f"(d.x), "+f"(d.y), "+f"(d.z), "+f"(d.w)
        : "r"(a.x), "r"(a.y), "r"(a.z), "r"(a.w), "r"(b0), "r"(b1));
}
__device__ __forceinline__ void ldm_x4(uint4& a, uint32_t addr) {
    asm volatile("ldmatrix.sync.aligned.m8n8.x4.shared.b16 {%0,%1,%2,%3}, [%4];"
        : "=r"(a.x), "=r"(a.y), "=r"(a.z), "=r"(a.w) : "r"(addr));
}
__device__ __forceinline__ float sq2(uint32_t h2, float acc) {
    float2 f = __half22float2(*(__half2*)&h2);
    return fmaf(f.x, f.x, fmaf(f.y, f.y, acc));
}

extern "C" __global__ void __launch_bounds__(THREADS, 2)
mobius_w12_kernel(const float* __restrict__ X,
                  const float* __restrict__ W,
                  const float* __restrict__ bias,
                  float* __restrict__ out,
                  int nrows)
{
    extern __shared__ __align__(16) char smem[];
    float* sbias = (float*)(smem + OFF_BIAS);
    float* sB2   = (float*)(smem + OFF_B2);
    float* xn2s  = (float*)(smem + OFF_XN2);
    float* rs2   = (float*)(smem + OFF_RS2);
    float* rsb   = (float*)(smem + OFF_RSB);
    float* cA    = (float*)(smem + OFF_CA);
    float* cB    = (float*)(smem + OFF_CB);

    const int tid  = threadIdx.x;
    const int lane = tid & 31;
    const int wid  = tid >> 5;        // 12 warps: 0-3 producers, 4-11 consumers
    const int g    = lane >> 2;
    const int cg   = lane & 3;

    if (tid < 128) sbias[tid] = bias[tid];

    // ---- W conversion (once, warps 0-7): warp wid = k-step s; fp16 ----
    if (wid < 8) {
        const float* wp0 = W + wid * 16 + 2 * cg;
        #pragma unroll
        for (int nt = 0; nt < 16; nt++) {
            int n = nt * 8 + g;
            const float* wp = wp0 + n * DIN;
            float2 u0 = *(const float2*)(wp);
            float2 u1 = *(const float2*)(wp + 8);
            uint2 vh;
            vh.x = packh(u0.y, u0.x);
            vh.y = packh(u1.y, u1.x);
            int p = nt >> 1, half = nt & 1;
            *(uint2*)(smem + OFF_WH + ((wid * 8 + p) * 32 + lane) * 16 + half * 8) = vh;
        }
    }
    __syncthreads();
    if (tid < 32) {
        float s = 0.f;
        #pragma unroll
        for (int i = 0; i < 4; i++) { float v = sbias[tid + 32 * i]; s = fmaf(v, v, s); }
        #pragma unroll
        for (int o = 16; o; o >>= 1) s += __shfl_xor_sync(0xffffffffu, s, o);
        if (tid == 0) *sB2 = s;
    }
    __syncthreads();   // last CTA-wide barrier

    const int ntiles = nrows / TILE;
    const int gstep  = gridDim.x;

    if (wid < 4) {
        // ===== PRODUCER: pure stream, coalesced rows -> swizzled fp16 =====
        const int p = wid;                // rows p*16 .. p*16+15
        const int ch0 = lane >> 1;
        const int sub = (lane & 1) * 8;
        int i = 0;
        for (int t = blockIdx.x; t < ntiles; t += gstep, i++) {
            const int st = i & (NST - 1);
            if (i >= NST) bar_sync(BAR_EMPTY(st), THREADS);

            const long long rowbase = (long long)t * TILE;
            const float* xp = X + (rowbase + p * 16) * DIN + lane * 4;
            char* abuf = smem + AH_ST(st);
            #pragma unroll
            for (int r = 0; r < 16; r++) {
                float4 v = *(const float4*)(xp + r * DIN);
                uint2 u;
                u.x = packh(v.y, v.x);
                u.y = packh(v.w, v.z);
                int rw = p * 16 + r;
                int sw = ch0 ^ (rw & 7);
                *(uint2*)(abuf + rw * 256 + sw * 16 + sub) = u;
            }
            __threadfence_block();
            bar_arrive(BAR_FULL(st), THREADS);
        }
    } else {
        // ===== CONSUMER (8 warps): m32 x n32 tiles + xn2 + epilogue =====
        const int c    = wid - 4;      // 0..7
        const int wm   = c >> 2;       // m-half (rows wm*32 .. wm*32+31)
        const int wn   = c & 3;        // n-quarter (cols wn*32 .. wn*32+31)
        const int ctid = tid - 128;    // 0..255
        const float b2c = *sB2;

        const int rloc = ((lane >> 3) & 1) * 8 + (lane & 7);
        const int hk   = lane >> 4;

        float2 bj[4];
        #pragma unroll
        for (int j = 0; j < 4; j++)
            bj[j] = *(const float2*)(sbias + wn * 32 + j * 8 + 2 * cg);

        int i = 0;
        for (int t = blockIdx.x; t < ntiles; t += gstep, i++) {
            const int st = i & (NST - 1);
            const long long rowbase = (long long)t * TILE;

            bar_sync(BAR_FULL(st), THREADS);

            const uint32_t abase = smem_u32(smem + AH_ST(st));

            // ---- mainloop: 1-pass fp16, warp tile m32 x n32 ----
            float4 acc[2][4];
            #pragma unroll
            for (int ii = 0; ii < 2; ii++)
                #pragma unroll
                for (int j = 0; j < 4; j++) acc[ii][j] = make_float4(0.f, 0.f, 0.f, 0.f);
            float xs2r0 = 0.f, xs2r1 = 0.f;

            #pragma unroll
            for (int s = 0; s < 8; s++) {
                uint4 ah[2], wh[2];
                #pragma unroll
                for (int ii = 0; ii < 2; ii++) {
                    int row = wm * 32 + ii * 16 + rloc;
                    int ch  = (s * 2 + hk) ^ (row & 7);
                    ldm_x4(ah[ii], abase + row * 256 + ch * 16);
                }
                #pragma unroll
                for (int u = 0; u < 2; u++)
                    wh[u] = *(const uint4*)(smem + OFF_WH
                              + ((s * 8 + wn * 2 + u) * 32 + lane) * 16);
                #pragma unroll
                for (int ii = 0; ii < 2; ii++)
                    #pragma unroll
                    for (int u = 0; u < 2; u++) {
                        mma_f16(acc[ii][2*u],   ah[ii], wh[u].x, wh[u].y);
                        mma_f16(acc[ii][2*u+1], ah[ii], wh[u].z, wh[u].w);
                    }
                // xn2 partials: warp (wm, wn<2) owns row block wm*2 + wn
                #pragma unroll
                for (int ii = 0; ii < 2; ii++) {
                    if (ii == wn) {          // only wn = 0,1 contribute
                        xs2r0 = sq2(ah[ii].x, xs2r0);
                        xs2r1 = sq2(ah[ii].y, xs2r1);
                        xs2r0 = sq2(ah[ii].z, xs2r0);
                        xs2r1 = sq2(ah[ii].w, xs2r1);
                    }
                }
            }

            // ---- reductions per row ----
            if (wn < 2) {
                xs2r0 += __shfl_xor_sync(0xffffffffu, xs2r0, 1);
                xs2r0 += __shfl_xor_sync(0xffffffffu, xs2r0, 2);
                xs2r1 += __shfl_xor_sync(0xffffffffu, xs2r1, 1);
                xs2r1 += __shfl_xor_sync(0xffffffffu, xs2r1, 2);
                if (cg == 0) {
                    int b = wm * 2 + wn;
                    xn2s[b * 16 + g]     = xs2r0;
                    xn2s[b * 16 + g + 8] = xs2r1;
                }
            }

            #pragma unroll
            for (int ii = 0; ii < 2; ii++) {
                float s2r0 = 0.f, s2r1 = 0.f, sbr0 = 0.f, sbr1 = 0.f;
                #pragma unroll
                for (int j = 0; j < 4; j++) {
                    float4 d = acc[ii][j];
                    s2r0 = fmaf(d.x, d.x, s2r0); s2r0 = fmaf(d.y, d.y, s2r0);
                    s2r1 = fmaf(d.z, d.z, s2r1); s2r1 = fmaf(d.w, d.w, s2r1);
                    sbr0 = fmaf(d.x, bj[j].x, sbr0); sbr0 = fmaf(d.y, bj[j].y, sbr0);
                    sbr1 = fmaf(d.z, bj[j].x, sbr1); sbr1 = fmaf(d.w, bj[j].y, sbr1);
                }
                s2r0 += __shfl_xor_sync(0xffffffffu, s2r0, 1);
                s2r0 += __shfl_xor_sync(0xffffffffu, s2r0, 2);
                s2r1 += __shfl_xor_sync(0xffffffffu, s2r1, 1);
                s2r1 += __shfl_xor_sync(0xffffffffu, s2r1, 2);
                sbr0 += __shfl_xor_sync(0xffffffffu, sbr0, 1);
                sbr0 += __shfl_xor_sync(0xffffffffu, sbr0, 2);
                sbr1 += __shfl_xor_sync(0xffffffffu, sbr1, 1);
                sbr1 += __shfl_xor_sync(0xffffffffu, sbr1, 2);
                if (cg == 0) {
                    int r0 = wm * 32 + ii * 16 + g;
                    rs2[r0 * 4 + wn]       = s2r0;
                    rs2[(r0 + 8) * 4 + wn] = s2r1;
                    rsb[r0 * 4 + wn]       = sbr0;
                    rsb[(r0 + 8) * 4 + wn] = sbr1;
                }
            }
            bar_sync(BAR_CONS, 256);

            // ---- per-row coefficients ----
            if (ctid < TILE) {
                int r = ctid;
                float4 a4 = *(const float4*)(rs2 + r * 4);
                float4 b4 = *(const float4*)(rsb + r * 4);
                float mxn2 = (a4.x + a4.y) + (a4.z + a4.w);
                float dotb = (b4.x + b4.y) + (b4.z + b4.w);
                float xn  = fmaxf(sqrtf(xn2s[r]), 1e-15f);
                float mxn = fmaxf(sqrtf(mxn2),    1e-15f);
                float u   = fminf(xn, 1.0f - 1e-7f);
                float at  = 0.5f * (log1pf(u) - log1pf(-u));
                float sc  = tanhf(mxn / xn * at) / mxn;
                if (mxn <= 1e-10f) sc = 0.0f;
                float xy    = sc * dotb;
                float y2    = sc * sc * mxn2;
                float alpha = 1.0f + 2.0f * xy + b2c;
                float beta  = 1.0f - y2;
                float den   = fmaxf(1.0f + 2.0f * xy + y2 * b2c, 1e-15f);
                float A  = sc * alpha / den;
                float Bc = beta / den;
                float o2 = A * A * mxn2 + 2.0f * A * Bc * dotb + Bc * Bc * b2c;
                float on = fmaxf(sqrtf(o2), 1e-15f);
                float mxv = 1.0f - 1e-5f;
                float fpr = (on > mxv) ? (mxv / on) : 1.0f;
                cA[r] = A * fpr;
                cB[r] = Bc * fpr;
            }
            bar_sync(BAR_CONS, 256);

            // stage fully consumed
            if (t + NST * gstep < ntiles)
                bar_arrive(BAR_EMPTY(st), THREADS);

            // ---- stores: out = A[r]*Mx + B[r]*bias from regs ----
            #pragma unroll
            for (int ii = 0; ii < 2; ii++) {
                int r0 = wm * 32 + ii * 16 + g;
                float A0 = cA[r0],     B0 = cB[r0];
                float A1 = cA[r0 + 8], B1 = cB[r0 + 8];
                float* op0 = out + (rowbase + r0) * DOUT + wn * 32 + 2 * cg;
                float* op1 = op0 + 8 * DOUT;
                #pragma unroll
                for (int j = 0; j < 4; j++) {
                    float4 d = acc[ii][j];
                    float2 o0, o1;
                    o0.x = fmaf(A0, d.x, B0 * bj[j].x);
                    o0.y = fmaf(A0, d.y, B0 * bj[j].y);
                    o1.x = fmaf(A1, d.z, B1 * bj[j].x);
                    o1.y = fmaf(A1, d.w, B1 * bj[j].y);
                    *(float2*)(op0 + j * 8) = o0;
                    *(float2*)(op1 + j * 8) = o1;
                }
            }
            // cA/cB/xn2 reuse safe: next writes happen after the next
            // BAR_CONS pair, which this warp reaches only after stores issue.
        }
    }
}

extern "C" void kernel_launch(void* const* d_in, const int* in_sizes, int n_in,
                              void* d_out, int out_size) {
    const float* X    = (const float*)d_in[0];
    const float* W    = (const float*)d_in[1];
    const float* bias = (const float*)d_in[2];
    float* out = (float*)d_out;

    int nrows = in_sizes[0] / DIN;

    cudaFuncSetAttribute(mobius_w12_kernel,
                         cudaFuncAttributeMaxDynamicSharedMemorySize, SMEM_TOTAL);

    int nsm = 148;
    cudaDeviceGetAttribute(&nsm, cudaDevAttrMultiProcessorCount, 0);
    int ntiles = nrows / TILE;
    int grid = 2 * nsm;
    if (grid > ntiles) grid = ntiles;

    mobius_w12_kernel<<<grid, THREADS, SMEM_TOTAL>>>(X, W, bias, out, nrows);
}